// round 1
// baseline (speedup 1.0000x reference)
#include <cuda_runtime.h>

#define NPTS 262144
#define NSAMP 8
#define CH 32
#define EPSD 1e-5

// ---------------- device scratch (static, no allocations) ----------------
__device__ float g_q[NPTS*CH];
__device__ float g_k[NPTS*CH];
__device__ float g_v[NPTS*CH];
__device__ float g_w1[NPTS*NSAMP*4];
__device__ double g_statP[9*16];    // padded 128B apart: sum d(3), sum dd (xx,yy,zz,xy,xz,yz)
__device__ double g_statW[64*16];   // sum[32], ssq[32]
__device__ double g_statW1[8*16];   // sum[4], ssq[4]
__device__ float g_foldP[12];       // A[3][3], B[3]
__device__ float g_foldW[64];       // s1[32], t1[32]
__device__ float g_foldW1[8];       // s2[4], t2[4]

// ---------------- zero the stat accumulators (runs every launch) ----------
__global__ void tf_init() {
    int t = threadIdx.x;
    if (t < 9)  g_statP[t*16]  = 0.0;
    if (t < 64) g_statW[t*16]  = 0.0;
    if (t < 8)  g_statW1[t*16] = 0.0;
}

// ---------------- K0: q,k,v projections + p-relative statistics ----------
__global__ void __launch_bounds__(256) tf_qkv(
    const float* __restrict__ x, const float* __restrict__ p, const int* __restrict__ idx,
    const float* __restrict__ Wq, const float* __restrict__ bq,
    const float* __restrict__ Wk, const float* __restrict__ bk,
    const float* __restrict__ Wv, const float* __restrict__ bv)
{
    __shared__ float sW[3*CH*CH];
    __shared__ float sB[3*CH];
    __shared__ float sRed[8][9];
    int tid = threadIdx.x;
    for (int i = tid; i < CH*CH; i += 256) {
        sW[i]           = Wq[i];
        sW[CH*CH + i]   = Wk[i];
        sW[2*CH*CH + i] = Wv[i];
    }
    if (tid < CH) { sB[tid] = bq[tid]; sB[CH+tid] = bk[tid]; sB[2*CH+tid] = bv[tid]; }
    __syncthreads();

    int n = blockIdx.x*256 + tid;
    float4 xr[8];
    const float4* xp = (const float4*)x + (size_t)n*8;
#pragma unroll
    for (int i = 0; i < 8; i++) xr[i] = xp[i];

#pragma unroll 1
    for (int m = 0; m < 3; m++) {
        float* dstb = (m == 0) ? g_q : (m == 1) ? g_k : g_v;
        float4* dst = (float4*)(dstb + (size_t)n*CH);
        const float4* W4 = (const float4*)(sW + m*CH*CH);
        const float* bb = sB + m*CH;
#pragma unroll 1
        for (int c = 0; c < CH; c += 4) {
            float a0 = bb[c], a1 = bb[c+1], a2 = bb[c+2], a3 = bb[c+3];
#pragma unroll
            for (int j = 0; j < 8; j++) {
                float4 xv = xr[j];
                float4 w0 = W4[(c+0)*8 + j];
                float4 w1 = W4[(c+1)*8 + j];
                float4 w2 = W4[(c+2)*8 + j];
                float4 w3 = W4[(c+3)*8 + j];
                a0 = fmaf(w0.x,xv.x,fmaf(w0.y,xv.y,fmaf(w0.z,xv.z,fmaf(w0.w,xv.w,a0))));
                a1 = fmaf(w1.x,xv.x,fmaf(w1.y,xv.y,fmaf(w1.z,xv.z,fmaf(w1.w,xv.w,a1))));
                a2 = fmaf(w2.x,xv.x,fmaf(w2.y,xv.y,fmaf(w2.z,xv.z,fmaf(w2.w,xv.w,a2))));
                a3 = fmaf(w3.x,xv.x,fmaf(w3.y,xv.y,fmaf(w3.z,xv.z,fmaf(w3.w,xv.w,a3))));
            }
            dst[c>>2] = make_float4(a0,a1,a2,a3);
        }
    }

    // statistics of d = p[idx] - p  (9 moments)
    float pnx = p[n*3+0], pny = p[n*3+1], pnz = p[n*3+2];
    float acc[9];
#pragma unroll
    for (int k = 0; k < 9; k++) acc[k] = 0.f;
#pragma unroll
    for (int s = 0; s < NSAMP; s++) {
        int i = idx[n*NSAMP + s];
        float dx = p[i*3+0]-pnx, dy = p[i*3+1]-pny, dz = p[i*3+2]-pnz;
        acc[0]+=dx; acc[1]+=dy; acc[2]+=dz;
        acc[3]=fmaf(dx,dx,acc[3]); acc[4]=fmaf(dy,dy,acc[4]); acc[5]=fmaf(dz,dz,acc[5]);
        acc[6]=fmaf(dx,dy,acc[6]); acc[7]=fmaf(dx,dz,acc[7]); acc[8]=fmaf(dy,dz,acc[8]);
    }
#pragma unroll
    for (int k = 0; k < 9; k++)
#pragma unroll
        for (int off = 16; off > 0; off >>= 1)
            acc[k] += __shfl_xor_sync(0xffffffffu, acc[k], off);
    int lane = tid & 31, w = tid >> 5;
    if (lane == 0) {
#pragma unroll
        for (int k = 0; k < 9; k++) sRed[w][k] = acc[k];
    }
    __syncthreads();
    if (tid < 9) {
        float t = 0.f;
#pragma unroll
        for (int w2 = 0; w2 < 8; w2++) t += sRed[w2][tid];
        atomicAdd(&g_statP[tid*16], (double)t);
    }
}

// ---------------- K1: fold BN(3) into affine relu(A.d + B) --------------
__global__ void tf_foldP(const float* __restrict__ Wp1, const float* __restrict__ bp1,
                         const float* __restrict__ gp,  const float* __restrict__ bp)
{
    if (threadIdx.x != 0) return;
    const double M = (double)NPTS * (double)NSAMP;
    double mu0 = g_statP[0*16]/M, mu1 = g_statP[1*16]/M, mu2 = g_statP[2*16]/M;
    double c00 = g_statP[3*16]/M - mu0*mu0;
    double c11 = g_statP[4*16]/M - mu1*mu1;
    double c22 = g_statP[5*16]/M - mu2*mu2;
    double c01 = g_statP[6*16]/M - mu0*mu1;
    double c02 = g_statP[7*16]/M - mu0*mu2;
    double c12 = g_statP[8*16]/M - mu1*mu2;
    for (int m = 0; m < 3; m++) {
        double a0 = Wp1[m*3+0], a1 = Wp1[m*3+1], a2 = Wp1[m*3+2];
        double var = a0*a0*c00 + a1*a1*c11 + a2*a2*c22
                   + 2.0*(a0*a1*c01 + a0*a2*c02 + a1*a2*c12);
        double sc = (double)gp[m] / sqrt(var + EPSD);
        double A0 = sc*a0, A1 = sc*a1, A2 = sc*a2;
        g_foldP[m*3+0] = (float)A0;
        g_foldP[m*3+1] = (float)A1;
        g_foldP[m*3+2] = (float)A2;
        g_foldP[9+m] = (float)((double)bp[m] - (A0*mu0 + A1*mu1 + A2*mu2));
    }
}

// ---------------- K2: accumulate BN(32) stats of w ------------------------
__global__ void __launch_bounds__(256) tf_wstat(
    const float* __restrict__ p, const int* __restrict__ idx,
    const float* __restrict__ Wp2, const float* __restrict__ bp2)
{
    __shared__ float sSum[CH], sSsq[CH];
    int tid = threadIdx.x;
    if (tid < CH) { sSum[tid] = 0.f; sSsq[tid] = 0.f; }
    __syncthreads();

    int lane = tid & 31, warp = tid >> 5;
    int g = lane >> 3, l = lane & 7;
    int nbase = (blockIdx.x*8 + warp)*4;
    int n = nbase + g;
    int c0 = 4*l;

    float A00=g_foldP[0],A01=g_foldP[1],A02=g_foldP[2];
    float A10=g_foldP[3],A11=g_foldP[4],A12=g_foldP[5];
    float A20=g_foldP[6],A21=g_foldP[7],A22=g_foldP[8];
    float B0=g_foldP[9],B1=g_foldP[10],B2=g_foldP[11];

    float W0x=Wp2[(c0+0)*3+0], W0y=Wp2[(c0+0)*3+1], W0z=Wp2[(c0+0)*3+2];
    float W1x=Wp2[(c0+1)*3+0], W1y=Wp2[(c0+1)*3+1], W1z=Wp2[(c0+1)*3+2];
    float W2x=Wp2[(c0+2)*3+0], W2y=Wp2[(c0+2)*3+1], W2z=Wp2[(c0+2)*3+2];
    float W3x=Wp2[(c0+3)*3+0], W3y=Wp2[(c0+3)*3+1], W3z=Wp2[(c0+3)*3+2];
    float b0=bp2[c0+0], b1=bp2[c0+1], b2=bp2[c0+2], b3=bp2[c0+3];

    float4 q4 = ((const float4*)g_q)[(size_t)n*8 + l];
    float pnx = p[n*3+0], pny = p[n*3+1], pnz = p[n*3+2];
    int myidx = idx[nbase*NSAMP + lane];

    // this lane owns neighbor s=l of point n: precompute relu(A.d+B)
    float dx = p[myidx*3+0]-pnx, dy = p[myidx*3+1]-pny, dz = p[myidx*3+2]-pnz;
    float r0 = fmaxf(fmaf(A02,dz,fmaf(A01,dy,fmaf(A00,dx,B0))), 0.f);
    float r1 = fmaxf(fmaf(A12,dz,fmaf(A11,dy,fmaf(A10,dx,B1))), 0.f);
    float r2 = fmaxf(fmaf(A22,dz,fmaf(A21,dy,fmaf(A20,dx,B2))), 0.f);

    float4 sum = make_float4(0,0,0,0), ssq = make_float4(0,0,0,0);
#pragma unroll
    for (int s = 0; s < NSAMP; s++) {
        int src = (g<<3) + s;
        int i   = __shfl_sync(0xffffffffu, myidx, src);
        float rr0 = __shfl_sync(0xffffffffu, r0, src);
        float rr1 = __shfl_sync(0xffffffffu, r1, src);
        float rr2 = __shfl_sync(0xffffffffu, r2, src);
        float4 kg = ((const float4*)g_k)[(size_t)i*8 + l];
        float pr0 = fmaf(W0z,rr2,fmaf(W0y,rr1,fmaf(W0x,rr0,b0)));
        float pr1 = fmaf(W1z,rr2,fmaf(W1y,rr1,fmaf(W1x,rr0,b1)));
        float pr2 = fmaf(W2z,rr2,fmaf(W2y,rr1,fmaf(W2x,rr0,b2)));
        float pr3 = fmaf(W3z,rr2,fmaf(W3y,rr1,fmaf(W3x,rr0,b3)));
        float w0 = kg.x - q4.x + pr0;
        float w1 = kg.y - q4.y + pr1;
        float w2 = kg.z - q4.z + pr2;
        float w3 = kg.w - q4.w + pr3;
        sum.x += w0; sum.y += w1; sum.z += w2; sum.w += w3;
        ssq.x = fmaf(w0,w0,ssq.x); ssq.y = fmaf(w1,w1,ssq.y);
        ssq.z = fmaf(w2,w2,ssq.z); ssq.w = fmaf(w3,w3,ssq.w);
    }
#pragma unroll
    for (int off = 8; off <= 16; off <<= 1) {
        sum.x += __shfl_xor_sync(0xffffffffu, sum.x, off);
        sum.y += __shfl_xor_sync(0xffffffffu, sum.y, off);
        sum.z += __shfl_xor_sync(0xffffffffu, sum.z, off);
        sum.w += __shfl_xor_sync(0xffffffffu, sum.w, off);
        ssq.x += __shfl_xor_sync(0xffffffffu, ssq.x, off);
        ssq.y += __shfl_xor_sync(0xffffffffu, ssq.y, off);
        ssq.z += __shfl_xor_sync(0xffffffffu, ssq.z, off);
        ssq.w += __shfl_xor_sync(0xffffffffu, ssq.w, off);
    }
    if (g == 0) {
        atomicAdd(&sSum[c0+0], sum.x); atomicAdd(&sSum[c0+1], sum.y);
        atomicAdd(&sSum[c0+2], sum.z); atomicAdd(&sSum[c0+3], sum.w);
        atomicAdd(&sSsq[c0+0], ssq.x); atomicAdd(&sSsq[c0+1], ssq.y);
        atomicAdd(&sSsq[c0+2], ssq.z); atomicAdd(&sSsq[c0+3], ssq.w);
    }
    __syncthreads();
    if (tid < CH) {
        atomicAdd(&g_statW[tid*16],        (double)sSum[tid]);
        atomicAdd(&g_statW[(CH+tid)*16],   (double)sSsq[tid]);
    }
}

// ---------------- K3: fold BN(32) -> s1,t1 --------------------------------
__global__ void tf_foldW(const float* __restrict__ gw1, const float* __restrict__ bw1)
{
    int c = threadIdx.x;
    if (c >= CH) return;
    const double M = (double)NPTS * (double)NSAMP;
    double mean = g_statW[c*16]/M;
    double var  = g_statW[(CH+c)*16]/M - mean*mean;
    double s = (double)gw1[c] / sqrt(var + EPSD);
    g_foldW[c]      = (float)s;
    g_foldW[CH + c] = (float)((double)bw1[c] - s*mean);
}

// ---------------- K4: compute w1, store, accumulate BN(4) stats -----------
__global__ void __launch_bounds__(256) tf_w1(
    const float* __restrict__ p, const int* __restrict__ idx,
    const float* __restrict__ Wp2, const float* __restrict__ bp2,
    const float* __restrict__ Ww1, const float* __restrict__ bww1)
{
    __shared__ float sSum[4], sSsq[4];
    int tid = threadIdx.x;
    if (tid < 4) { sSum[tid] = 0.f; sSsq[tid] = 0.f; }
    __syncthreads();

    int lane = tid & 31, warp = tid >> 5;
    int g = lane >> 3, l = lane & 7;
    int nbase = (blockIdx.x*8 + warp)*4;
    int n = nbase + g;
    int c0 = 4*l;

    float A00=g_foldP[0],A01=g_foldP[1],A02=g_foldP[2];
    float A10=g_foldP[3],A11=g_foldP[4],A12=g_foldP[5];
    float A20=g_foldP[6],A21=g_foldP[7],A22=g_foldP[8];
    float B0=g_foldP[9],B1=g_foldP[10],B2=g_foldP[11];

    float W0x=Wp2[(c0+0)*3+0], W0y=Wp2[(c0+0)*3+1], W0z=Wp2[(c0+0)*3+2];
    float W1x=Wp2[(c0+1)*3+0], W1y=Wp2[(c0+1)*3+1], W1z=Wp2[(c0+1)*3+2];
    float W2x=Wp2[(c0+2)*3+0], W2y=Wp2[(c0+2)*3+1], W2z=Wp2[(c0+2)*3+2];
    float W3x=Wp2[(c0+3)*3+0], W3y=Wp2[(c0+3)*3+1], W3z=Wp2[(c0+3)*3+2];
    float b0=bp2[c0+0], b1=bp2[c0+1], b2=bp2[c0+2], b3=bp2[c0+3];

    float4 s1 = ((const float4*)g_foldW)[l];
    float4 t1 = ((const float4*)(g_foldW + CH))[l];
    float4 u0 = ((const float4*)Ww1)[0*8 + l];
    float4 u1 = ((const float4*)Ww1)[1*8 + l];
    float4 u2 = ((const float4*)Ww1)[2*8 + l];
    float4 u3 = ((const float4*)Ww1)[3*8 + l];
    float bb0 = bww1[0], bb1 = bww1[1], bb2 = bww1[2], bb3 = bww1[3];

    float4 q4 = ((const float4*)g_q)[(size_t)n*8 + l];
    float pnx = p[n*3+0], pny = p[n*3+1], pnz = p[n*3+2];
    int myidx = idx[nbase*NSAMP + lane];

    float dx = p[myidx*3+0]-pnx, dy = p[myidx*3+1]-pny, dz = p[myidx*3+2]-pnz;
    float r0 = fmaxf(fmaf(A02,dz,fmaf(A01,dy,fmaf(A00,dx,B0))), 0.f);
    float r1 = fmaxf(fmaf(A12,dz,fmaf(A11,dy,fmaf(A10,dx,B1))), 0.f);
    float r2 = fmaxf(fmaf(A22,dz,fmaf(A21,dy,fmaf(A20,dx,B2))), 0.f);

    float ss0=0,ss1=0,ss2=0,ss3=0, sq0=0,sq1=0,sq2=0,sq3=0;
#pragma unroll
    for (int s = 0; s < NSAMP; s++) {
        int src = (g<<3) + s;
        int i   = __shfl_sync(0xffffffffu, myidx, src);
        float rr0 = __shfl_sync(0xffffffffu, r0, src);
        float rr1 = __shfl_sync(0xffffffffu, r1, src);
        float rr2 = __shfl_sync(0xffffffffu, r2, src);
        float4 kg = ((const float4*)g_k)[(size_t)i*8 + l];
        float pr0 = fmaf(W0z,rr2,fmaf(W0y,rr1,fmaf(W0x,rr0,b0)));
        float pr1 = fmaf(W1z,rr2,fmaf(W1y,rr1,fmaf(W1x,rr0,b1)));
        float pr2 = fmaf(W2z,rr2,fmaf(W2y,rr1,fmaf(W2x,rr0,b2)));
        float pr3 = fmaf(W3z,rr2,fmaf(W3y,rr1,fmaf(W3x,rr0,b3)));
        float w0 = kg.x - q4.x + pr0;
        float w1 = kg.y - q4.y + pr1;
        float w2 = kg.z - q4.z + pr2;
        float w3 = kg.w - q4.w + pr3;
        float h0 = fmaxf(fmaf(s1.x, w0, t1.x), 0.f);
        float h1 = fmaxf(fmaf(s1.y, w1, t1.y), 0.f);
        float h2 = fmaxf(fmaf(s1.z, w2, t1.z), 0.f);
        float h3 = fmaxf(fmaf(s1.w, w3, t1.w), 0.f);
        float d0 = fmaf(u0.w,h3,fmaf(u0.z,h2,fmaf(u0.y,h1,u0.x*h0)));
        float d1 = fmaf(u1.w,h3,fmaf(u1.z,h2,fmaf(u1.y,h1,u1.x*h0)));
        float d2 = fmaf(u2.w,h3,fmaf(u2.z,h2,fmaf(u2.y,h1,u2.x*h0)));
        float d3 = fmaf(u3.w,h3,fmaf(u3.z,h2,fmaf(u3.y,h1,u3.x*h0)));
#pragma unroll
        for (int off = 1; off < 8; off <<= 1) {
            d0 += __shfl_xor_sync(0xffffffffu, d0, off);
            d1 += __shfl_xor_sync(0xffffffffu, d1, off);
            d2 += __shfl_xor_sync(0xffffffffu, d2, off);
            d3 += __shfl_xor_sync(0xffffffffu, d3, off);
        }
        if (l == 0) {
            float w10 = d0 + bb0, w11 = d1 + bb1, w12 = d2 + bb2, w13 = d3 + bb3;
            ((float4*)g_w1)[(size_t)n*NSAMP + s] = make_float4(w10,w11,w12,w13);
            ss0 += w10; ss1 += w11; ss2 += w12; ss3 += w13;
            sq0 = fmaf(w10,w10,sq0); sq1 = fmaf(w11,w11,sq1);
            sq2 = fmaf(w12,w12,sq2); sq3 = fmaf(w13,w13,sq3);
        }
    }
#pragma unroll
    for (int off = 8; off <= 16; off <<= 1) {
        ss0 += __shfl_xor_sync(0xffffffffu, ss0, off);
        ss1 += __shfl_xor_sync(0xffffffffu, ss1, off);
        ss2 += __shfl_xor_sync(0xffffffffu, ss2, off);
        ss3 += __shfl_xor_sync(0xffffffffu, ss3, off);
        sq0 += __shfl_xor_sync(0xffffffffu, sq0, off);
        sq1 += __shfl_xor_sync(0xffffffffu, sq1, off);
        sq2 += __shfl_xor_sync(0xffffffffu, sq2, off);
        sq3 += __shfl_xor_sync(0xffffffffu, sq3, off);
    }
    if (lane == 0) {
        atomicAdd(&sSum[0], ss0); atomicAdd(&sSum[1], ss1);
        atomicAdd(&sSum[2], ss2); atomicAdd(&sSum[3], ss3);
        atomicAdd(&sSsq[0], sq0); atomicAdd(&sSsq[1], sq1);
        atomicAdd(&sSsq[2], sq2); atomicAdd(&sSsq[3], sq3);
    }
    __syncthreads();
    if (tid < 4) {
        atomicAdd(&g_statW1[tid*16],     (double)sSum[tid]);
        atomicAdd(&g_statW1[(4+tid)*16], (double)sSsq[tid]);
    }
}

// ---------------- K5: fold BN(4) -> s2,t2 ---------------------------------
__global__ void tf_foldW1(const float* __restrict__ gw2, const float* __restrict__ bw2)
{
    int c = threadIdx.x;
    if (c >= 4) return;
    const double M = (double)NPTS * (double)NSAMP;
    double mean = g_statW1[c*16]/M;
    double var  = g_statW1[(4+c)*16]/M - mean*mean;
    double s = (double)gw2[c] / sqrt(var + EPSD);
    g_foldW1[c]     = (float)s;
    g_foldW1[4 + c] = (float)((double)bw2[c] - s*mean);
}

// ---------------- K6: softmax weights + weighted sum of (v + p_r2) --------
__global__ void __launch_bounds__(256) tf_out(
    const float* __restrict__ p, const int* __restrict__ idx,
    const float* __restrict__ Wp2, const float* __restrict__ bp2,
    const float* __restrict__ Ww2, const float* __restrict__ bww2,
    float* __restrict__ out)
{
    int tid = threadIdx.x;
    int lane = tid & 31, warp = tid >> 5;
    int g = lane >> 3, l = lane & 7;
    int nbase = (blockIdx.x*8 + warp)*4;
    int n = nbase + g;
    int c0 = 4*l;

    float A00=g_foldP[0],A01=g_foldP[1],A02=g_foldP[2];
    float A10=g_foldP[3],A11=g_foldP[4],A12=g_foldP[5];
    float A20=g_foldP[6],A21=g_foldP[7],A22=g_foldP[8];
    float B0=g_foldP[9],B1=g_foldP[10],B2=g_foldP[11];

    float W0x=Wp2[(c0+0)*3+0], W0y=Wp2[(c0+0)*3+1], W0z=Wp2[(c0+0)*3+2];
    float W1x=Wp2[(c0+1)*3+0], W1y=Wp2[(c0+1)*3+1], W1z=Wp2[(c0+1)*3+2];
    float W2x=Wp2[(c0+2)*3+0], W2y=Wp2[(c0+2)*3+1], W2z=Wp2[(c0+2)*3+2];
    float W3x=Wp2[(c0+3)*3+0], W3y=Wp2[(c0+3)*3+1], W3z=Wp2[(c0+3)*3+2];
    float b0=bp2[c0+0], b1=bp2[c0+1], b2=bp2[c0+2], b3=bp2[c0+3];

    float s20=g_foldW1[0], s21=g_foldW1[1], s22=g_foldW1[2], s23=g_foldW1[3];
    float t20=g_foldW1[4], t21=g_foldW1[5], t22=g_foldW1[6], t23=g_foldW1[7];
    float v2[16];
#pragma unroll
    for (int i = 0; i < 16; i++) v2[i] = Ww2[i];
    float bb0 = bww2[0], bb1 = bww2[1], bb2 = bww2[2], bb3 = bww2[3];

    float pnx = p[n*3+0], pny = p[n*3+1], pnz = p[n*3+2];
    int myidx = idx[nbase*NSAMP + lane];

    float dx = p[myidx*3+0]-pnx, dy = p[myidx*3+1]-pny, dz = p[myidx*3+2]-pnz;
    float r0 = fmaxf(fmaf(A02,dz,fmaf(A01,dy,fmaf(A00,dx,B0))), 0.f);
    float r1 = fmaxf(fmaf(A12,dz,fmaf(A11,dy,fmaf(A10,dx,B1))), 0.f);
    float r2 = fmaxf(fmaf(A22,dz,fmaf(A21,dy,fmaf(A20,dx,B2))), 0.f);

    // this lane owns s=l: compute logits for its sample
    float4 w14 = ((const float4*)g_w1)[(size_t)n*NSAMP + l];
    float y0 = fmaxf(fmaf(s20, w14.x, t20), 0.f);
    float y1 = fmaxf(fmaf(s21, w14.y, t21), 0.f);
    float y2 = fmaxf(fmaf(s22, w14.z, t22), 0.f);
    float y3 = fmaxf(fmaf(s23, w14.w, t23), 0.f);
    float lg0 = fmaf(v2[3], y3, fmaf(v2[2], y2, fmaf(v2[1], y1, fmaf(v2[0], y0, bb0))));
    float lg1 = fmaf(v2[7], y3, fmaf(v2[6], y2, fmaf(v2[5], y1, fmaf(v2[4], y0, bb1))));
    float lg2 = fmaf(v2[11],y3, fmaf(v2[10],y2, fmaf(v2[9], y1, fmaf(v2[8], y0, bb2))));
    float lg3 = fmaf(v2[15],y3, fmaf(v2[14],y2, fmaf(v2[13],y1, fmaf(v2[12],y0, bb3))));

    // softmax over s (8 lanes per group), per output channel j
    float m0=lg0, m1=lg1, m2=lg2, m3=lg3;
#pragma unroll
    for (int off = 1; off < 8; off <<= 1) {
        m0 = fmaxf(m0, __shfl_xor_sync(0xffffffffu, m0, off));
        m1 = fmaxf(m1, __shfl_xor_sync(0xffffffffu, m1, off));
        m2 = fmaxf(m2, __shfl_xor_sync(0xffffffffu, m2, off));
        m3 = fmaxf(m3, __shfl_xor_sync(0xffffffffu, m3, off));
    }
    float e0 = __expf(lg0 - m0);
    float e1 = __expf(lg1 - m1);
    float e2 = __expf(lg2 - m2);
    float e3 = __expf(lg3 - m3);
    float z0=e0, z1=e1, z2=e2, z3=e3;
#pragma unroll
    for (int off = 1; off < 8; off <<= 1) {
        z0 += __shfl_xor_sync(0xffffffffu, z0, off);
        z1 += __shfl_xor_sync(0xffffffffu, z1, off);
        z2 += __shfl_xor_sync(0xffffffffu, z2, off);
        z3 += __shfl_xor_sync(0xffffffffu, z3, off);
    }
    float ws0 = __fdividef(e0, z0);
    float ws1 = __fdividef(e1, z1);
    float ws2 = __fdividef(e2, z2);
    float ws3 = __fdividef(e3, z3);

    float4 acc = make_float4(0,0,0,0);
#pragma unroll
    for (int s = 0; s < NSAMP; s++) {
        int src = (g<<3) + s;
        int i   = __shfl_sync(0xffffffffu, myidx, src);
        float rr0 = __shfl_sync(0xffffffffu, r0, src);
        float rr1 = __shfl_sync(0xffffffffu, r1, src);
        float rr2 = __shfl_sync(0xffffffffu, r2, src);
        float a0 = __shfl_sync(0xffffffffu, ws0, src);
        float a1 = __shfl_sync(0xffffffffu, ws1, src);
        float a2 = __shfl_sync(0xffffffffu, ws2, src);
        float a3 = __shfl_sync(0xffffffffu, ws3, src);
        float4 vg = ((const float4*)g_v)[(size_t)i*8 + l];
        float pr0 = fmaf(W0z,rr2,fmaf(W0y,rr1,fmaf(W0x,rr0,b0)));
        float pr1 = fmaf(W1z,rr2,fmaf(W1y,rr1,fmaf(W1x,rr0,b1)));
        float pr2 = fmaf(W2z,rr2,fmaf(W2y,rr1,fmaf(W2x,rr0,b2)));
        float pr3 = fmaf(W3z,rr2,fmaf(W3y,rr1,fmaf(W3x,rr0,b3)));
        acc.x = fmaf(vg.x + pr0, a0, acc.x);
        acc.y = fmaf(vg.y + pr1, a1, acc.y);
        acc.z = fmaf(vg.z + pr2, a2, acc.z);
        acc.w = fmaf(vg.w + pr3, a3, acc.w);
    }
    ((float4*)out)[(size_t)n*8 + l] = acc;
}

// --------------------------------------------------------------------------
extern "C" void kernel_launch(void* const* d_in, const int* in_sizes, int n_in,
                              void* d_out, int out_size)
{
    const float* p    = (const float*)d_in[0];
    const float* x    = (const float*)d_in[1];
    const int*   idx  = (const int*)  d_in[2];
    const float* Wq   = (const float*)d_in[3];
    const float* bq   = (const float*)d_in[4];
    const float* Wk   = (const float*)d_in[5];
    const float* bk   = (const float*)d_in[6];
    const float* Wv   = (const float*)d_in[7];
    const float* bv   = (const float*)d_in[8];
    const float* Wp1  = (const float*)d_in[9];
    const float* bp1  = (const float*)d_in[10];
    const float* gp   = (const float*)d_in[11];
    const float* bp   = (const float*)d_in[12];
    const float* Wp2  = (const float*)d_in[13];
    const float* bp2  = (const float*)d_in[14];
    const float* gw1  = (const float*)d_in[15];
    const float* bw1  = (const float*)d_in[16];
    const float* Ww1  = (const float*)d_in[17];
    const float* bww1 = (const float*)d_in[18];
    const float* gw2  = (const float*)d_in[19];
    const float* bw2  = (const float*)d_in[20];
    const float* Ww2  = (const float*)d_in[21];
    const float* bww2 = (const float*)d_in[22];
    float* out = (float*)d_out;

    tf_init<<<1, 64>>>();
    tf_qkv<<<NPTS/256, 256>>>(x, p, idx, Wq, bq, Wk, bk, Wv, bv);
    tf_foldP<<<1, 32>>>(Wp1, bp1, gp, bp);
    tf_wstat<<<NPTS/32, 256>>>(p, idx, Wp2, bp2);
    tf_foldW<<<1, 32>>>(gw1, bw1);
    tf_w1<<<NPTS/32, 256>>>(p, idx, Wp2, bp2, Ww1, bww1);
    tf_foldW1<<<1, 32>>>(gw2, bw2);
    tf_out<<<NPTS/32, 256>>>(p, idx, Wp2, bp2, Ww2, bww2, out);
}